// round 13
// baseline (speedup 1.0000x reference)
#include <cuda_runtime.h>
#include <math.h>
#include <stdint.h>

// Problem shapes (fixed): B=2, T=1024, D=1024, N=8, HD=128, K=32

// ---------------- scratch (device globals; no allocation allowed) ----------
__device__ float g_qv  [2048u * 2048u];  // rows = b*1024+t, [0,1024)=q, [1024,2048)=v
__device__ float g_encB[2u * 1024u * 1024u]; // rna(enc_q)+rna(enc_v)
__device__ float g_decB[1024u * 1024u];      // rna(decoder)
__device__ float g_hebB[8u * 128u * 128u];   // rna(hebbian)
__device__ float g_sigp[8u * 1024u];     // sig partials: [mt(256-row tiles)][ct*128+c]
__device__ float g_h1p [16u * 1024u];    // mlp1 partials: [dchunk][b*512+j]
__device__ float g_h   [1024];           // [2][512]
__device__ float g_h2p [8u * 2048u];     // mlp2 partials: [ichunk][b*1024+j]
__device__ float g_md  [2048];           // [2][1024]
__device__ float g_heb [2048u * 1024u];  // hebbian context (un-normalized q basis)
__device__ float g_g   [2048u * 1024u];  // rna(q*(context+heb))
__device__ unsigned g_c1 = 0, g_c2 = 0;  // last-block counters (self-resetting)

// ---------------- helpers ----------------------------------------------------
__device__ __forceinline__ uint32_t smem_u32(const void* p) {
    uint32_t a;
    asm("{ .reg .u64 t; cvta.to.shared.u64 t, %1; cvt.u32.u64 %0, t; }" : "=r"(a) : "l"(p));
    return a;
}
__device__ __forceinline__ uint32_t rna_bits(float x) {
    uint32_t u; asm("cvt.rna.tf32.f32 %0, %1;" : "=r"(u) : "f"(x));
    return u;
}
__device__ __forceinline__ float rna_f(float x) {
    return __uint_as_float(rna_bits(x));
}
__device__ __forceinline__ void cp16(uint32_t dst, const void* src) {
    asm volatile("cp.async.cg.shared.global [%0], [%1], 16;" :: "r"(dst), "l"(src) : "memory");
}
__device__ __forceinline__ void mma_tf32_16n8k8(float* c, const uint32_t* a, const uint32_t* b) {
    asm volatile(
        "mma.sync.aligned.m16n8k8.row.col.f32.tf32.tf32.f32 "
        "{%0,%1,%2,%3}, {%4,%5,%6,%7}, {%8,%9}, {%0,%1,%2,%3};"
        : "+f"(c[0]), "+f"(c[1]), "+f"(c[2]), "+f"(c[3])
        : "r"(a[0]), "r"(a[1]), "r"(a[2]), "r"(a[3]), "r"(b[0]), "r"(b[1]));
}

// ---------------- pre-round: two tensors per launch --------------------------
__global__ void round2_kernel(const float4* __restrict__ s1, float4* __restrict__ d1, int n1,
                              const float4* __restrict__ s2, float4* __restrict__ d2, int n2)
{
    const int total = n1 + n2;
    for (int i = blockIdx.x * 256 + threadIdx.x; i < total; i += gridDim.x * 256) {
        const float4* s; float4* d; int j;
        if (i < n1) { s = s1; d = d1; j = i; }
        else        { s = s2; d = d2; j = i - n1; }
        float4 v = s[j];
        v.x = rna_f(v.x); v.y = rna_f(v.y);
        v.z = rna_f(v.z); v.w = rna_f(v.w);
        d[j] = v;
    }
}

// ---------------- tf32 mma.sync GEMM core -----------------------------------
// Block tile (64*MT) x 128, BK=32, 256 threads (8 warps: 4 in M x 2 in N),
// warp tile (16*MT) x 64. A row-major [.,lda], B row-major [K][N] (ldb).
// CVT_A/CVT_B: whether to RNA-round fragments at load (false = operand already
// tf32-rounded in gmem; HW truncation is then the identity).
#define A_STRIDE 36
#define B_STRIDE 136
#define B_SZ (32 * B_STRIDE)

template<int MT, bool RELU, bool CVT_A, bool CVT_B>
__device__ void gemm_mma_core(const float* __restrict__ A, int lda,
                              const float* __restrict__ B, int ldb,
                              float* __restrict__ C, int ldc, int Kdim,
                              float* __restrict__ sigp)
{
    extern __shared__ float smem[];
    constexpr int ROWS = 64 * MT;
    constexpr int ASZ  = ROWS * A_STRIDE;
    constexpr int STG  = ASZ + B_SZ;

    const int tid  = threadIdx.x;
    const int lane = tid & 31;
    const int wid  = tid >> 5;
    const int wm   = wid & 3;          // 0..3 -> (16*MT)-row slab
    const int wn   = wid >> 2;         // 0..1 -> 64-col slab
    const int grp  = lane >> 2;        // 0..7
    const int tig  = lane & 3;         // 0..3

    float acc[MT][8][4];
#pragma unroll
    for (int mt = 0; mt < MT; mt++)
#pragma unroll
        for (int nt = 0; nt < 8; nt++)
#pragma unroll
            for (int q = 0; q < 4; q++) acc[mt][nt][q] = 0.f;

    const int niter = Kdim >> 5;

    auto load_stage = [&](int S, int K0) {
        float* As_ = smem + S * STG;
        float* Bs_ = As_ + ASZ;
#pragma unroll
        for (int it = 0; it < 2 * MT; it++) {
            const int idx = tid + (it << 8);
            const int r_  = idx >> 3, c4_ = idx & 7;
            cp16(smem_u32(As_ + r_ * A_STRIDE + (c4_ << 2)),
                 A + (size_t)r_ * lda + K0 + (c4_ << 2));
        }
#pragma unroll
        for (int it = 0; it < 4; it++) {
            const int idx = tid + (it << 8);
            const int k_ = idx >> 5, n4_ = idx & 31;
            cp16(smem_u32(Bs_ + k_ * B_STRIDE + (n4_ << 2)),
                 B + (size_t)(K0 + k_) * ldb + (n4_ << 2));
        }
        asm volatile("cp.async.commit_group;" ::: "memory");
    };

    load_stage(0, 0);

#pragma unroll 1
    for (int j = 0; j < niter; j++) {
        if (j + 1 < niter) {
            load_stage((j + 1) & 1, (j + 1) << 5);
            asm volatile("cp.async.wait_group 1;" ::: "memory");
        } else {
            asm volatile("cp.async.wait_group 0;" ::: "memory");
        }
        __syncthreads();

        const float* As = smem + (j & 1) * STG;
        const float* Bs = As + ASZ;

#pragma unroll
        for (int kk = 0; kk < 4; kk++) {
            const int kb = kk << 3;
            uint32_t af[MT][4];
#pragma unroll
            for (int mt = 0; mt < MT; mt++) {
                const int r = wm * (16 * MT) + mt * 16 + grp;
                const float* ap = As + r * A_STRIDE + kb + tig;
                if (CVT_A) {
                    af[mt][0] = rna_bits(ap[0]);
                    af[mt][1] = rna_bits(ap[8 * A_STRIDE]);
                    af[mt][2] = rna_bits(ap[4]);
                    af[mt][3] = rna_bits(ap[8 * A_STRIDE + 4]);
                } else {
                    af[mt][0] = __float_as_uint(ap[0]);
                    af[mt][1] = __float_as_uint(ap[8 * A_STRIDE]);
                    af[mt][2] = __float_as_uint(ap[4]);
                    af[mt][3] = __float_as_uint(ap[8 * A_STRIDE + 4]);
                }
            }
            uint32_t bf[8][2];
#pragma unroll
            for (int nt = 0; nt < 8; nt++) {
                const int cc = wn * 64 + nt * 8 + grp;
                const float* bp = Bs + (kb + tig) * B_STRIDE + cc;
                if (CVT_B) {
                    bf[nt][0] = rna_bits(bp[0]);
                    bf[nt][1] = rna_bits(bp[4 * B_STRIDE]);
                } else {
                    bf[nt][0] = __float_as_uint(bp[0]);
                    bf[nt][1] = __float_as_uint(bp[4 * B_STRIDE]);
                }
            }
#pragma unroll
            for (int mt = 0; mt < MT; mt++)
#pragma unroll
                for (int nt = 0; nt < 8; nt++)
                    mma_tf32_16n8k8(acc[mt][nt], af[mt], bf[nt]);
        }
        __syncthreads();
    }

    // epilogue (+ optional fused sig accumulation)
    float csum[8][2];
#pragma unroll
    for (int nt = 0; nt < 8; nt++) { csum[nt][0] = 0.f; csum[nt][1] = 0.f; }

#pragma unroll
    for (int mt = 0; mt < MT; mt++) {
        const int r0 = wm * (16 * MT) + mt * 16 + grp;
#pragma unroll
        for (int nt = 0; nt < 8; nt++) {
            const int c0 = wn * 64 + nt * 8 + tig * 2;
            float2 v0 = make_float2(acc[mt][nt][0], acc[mt][nt][1]);
            float2 v1 = make_float2(acc[mt][nt][2], acc[mt][nt][3]);
            if (RELU) {
                v0.x = fmaxf(v0.x, 0.f); v0.y = fmaxf(v0.y, 0.f);
                v1.x = fmaxf(v1.x, 0.f); v1.y = fmaxf(v1.y, 0.f);
            }
            if (sigp) {
                csum[nt][0] += v0.x + v1.x;
                csum[nt][1] += v0.y + v1.y;
            }
            *(float2*)(C + (size_t)r0 * ldc + c0)       = v0;
            *(float2*)(C + (size_t)(r0 + 8) * ldc + c0) = v1;
        }
    }

    if (sigp) {
        // thread's rows are all == grp (mod 8) -> uniform time-weight
        const float w = (1.0f / 1024.0f) + ((grp == 0) ? (0.5f / 128.0f) : 0.f);
        float* sred = smem;      // safe: all threads past final k-loop sync
        if (tid < 128) sred[tid] = 0.f;
        __syncthreads();
#pragma unroll
        for (int nt = 0; nt < 8; nt++) {
            atomicAdd(&sred[wn * 64 + nt * 8 + tig * 2],     w * csum[nt][0]);
            atomicAdd(&sred[wn * 64 + nt * 8 + tig * 2 + 1], w * csum[nt][1]);
        }
        __syncthreads();
        if (tid < 128) sigp[tid] = sred[tid];   // non-atomic: block owns slot
    }
}

#define SMEM_MT2 (2 * (128 * A_STRIDE + B_SZ) * 4)   // 71680 B
#define SMEM_MT4 (2 * (256 * A_STRIDE + B_SZ) * 4)   // 108544 B

// enc: 256x128 tiles (MT=4). grid (16 ct, 8 mt).  A=x raw (cvt), B pre-rounded.
__global__ __launch_bounds__(256) void gemm_enc_kernel(const float* __restrict__ x)
{
    const int ct = blockIdx.x;   // 0..15: q heads then v heads
    const int mt = blockIdx.y;   // 0..7 (256-row tiles)
    const float* Bp = g_encB + (size_t)ct * 1024 * 128;
    float* sigp = (ct < 8) ? (g_sigp + mt * 1024 + ct * 128) : nullptr;
    gemm_mma_core<4, true, true, false>(x + (size_t)mt * 256 * 1024, 1024, Bp, 128,
                           g_qv + (size_t)mt * 256 * 2048 + ct * 128, 2048, 1024, sigp);
}
// dec: 128x128 tiles (MT=2). A=g_g pre-rounded (window), B pre-rounded.
__global__ __launch_bounds__(256) void gemm_dec_kernel(float* __restrict__ out)
{
    const int nt = blockIdx.x;   // 0..7
    const int mt = blockIdx.y;   // 0..15
    gemm_mma_core<2, false, false, false>(g_g + (size_t)mt * 128 * 1024, 1024,
                            g_decB + nt * 128, 1024,
                            out + (size_t)mt * 128 * 1024 + nt * 128, 1024, 1024, nullptr);
}
// heb: 128x128 tiles (MT=2). A=raw q (cvt; normalization deferred), B pre-rounded.
__global__ __launch_bounds__(256) void gemm_heb_kernel()
{
    const int n  = blockIdx.x;   // 0..7 head
    const int mt = blockIdx.y;   // 0..15
    gemm_mma_core<2, false, true, false>(g_qv + (size_t)mt * 128 * 2048 + n * 128, 2048,
                            g_hebB + (size_t)n * 128 * 128, 128,
                            g_heb + (size_t)mt * 128 * 1024 + n * 128, 1024, 128, nullptr);
}

// ---------------- MLP layer 1: partial GEMM + last-block finish -------------
// grid 32: bid = jb (0..1) | dc<<1 (0..15).  256 threads: one j each, both b.
__global__ void mlp1_kernel(const float* __restrict__ W1, const float* __restrict__ b1)
{
    __shared__ float ssig[2][64];
    __shared__ bool is_last;
    const int tid = threadIdx.x;
    const int jb  = blockIdx.x & 1;
    const int dc  = blockIdx.x >> 1;

    // gather sig chunk: sum 4 tile-partials per (b, d)  (256-row tiles)
    if (tid < 128) {
        const int b = tid >> 6, dl = tid & 63;
        float s = 0.f;
#pragma unroll
        for (int m = 0; m < 4; m++)
            s += g_sigp[(b * 4 + m) * 1024 + dc * 64 + dl];
        ssig[b][dl] = s;
    }
    __syncthreads();

    const int j = jb * 256 + tid;
    float acc0 = 0.f, acc1 = 0.f;
#pragma unroll 8
    for (int dd = 0; dd < 64; dd++) {
        const float w = __ldg(W1 + (size_t)(dc * 64 + dd) * 512 + j);
        acc0 = fmaf(ssig[0][dd], w, acc0);
        acc1 = fmaf(ssig[1][dd], w, acc1);
    }
    g_h1p[dc * 1024 + j]       = acc0;
    g_h1p[dc * 1024 + 512 + j] = acc1;

    __threadfence();
    if (tid == 0) is_last = (atomicAdd(&g_c1, 1u) == 31u);
    __syncthreads();
    if (is_last) {
#pragma unroll
        for (int q = 0; q < 4; q++) {
            const int i = q * 256 + tid;       // 0..1023 = b*512+j
            float a = b1[i & 511];
#pragma unroll
            for (int c = 0; c < 16; c++) a += g_h1p[c * 1024 + i];
            g_h[i] = 0.5f * a * (1.f + erff(a * 0.70710678118654752f));
        }
        __threadfence();
        if (tid == 0) g_c1 = 0u;
    }
}

// ---------------- MLP layer 2: partial GEMM + last-block finish -------------
// grid 32: bid = jb (0..3) | ic<<2 (0..7).  256 threads.
__global__ void mlp2_kernel(const float* __restrict__ W2, const float* __restrict__ b2,
                            const float* __restrict__ base_metric)
{
    __shared__ float sh[2][64];
    __shared__ bool is_last;
    const int tid = threadIdx.x;
    const int jb  = blockIdx.x & 3;
    const int ic  = blockIdx.x >> 2;

    if (tid < 128) {
        const int b = tid >> 6, il = tid & 63;
        sh[b][il] = g_h[b * 512 + ic * 64 + il];
    }
    __syncthreads();

    const int j = jb * 256 + tid;
    float acc0 = 0.f, acc1 = 0.f;
#pragma unroll 8
    for (int ii = 0; ii < 64; ii++) {
        const float w = __ldg(W2 + (size_t)(ic * 64 + ii) * 1024 + j);
        acc0 = fmaf(sh[0][ii], w, acc0);
        acc1 = fmaf(sh[1][ii], w, acc1);
    }
    g_h2p[ic * 2048 + j]        = acc0;
    g_h2p[ic * 2048 + 1024 + j] = acc1;

    __threadfence();
    if (tid == 0) is_last = (atomicAdd(&g_c2, 1u) == 31u);
    __syncthreads();
    if (is_last) {
#pragma unroll
        for (int q = 0; q < 8; q++) {
            const int i = q * 256 + tid;       // 0..2047 = b*1024+j
            const int jj = i & 1023;
            float mod = b2[jj];
#pragma unroll
            for (int c = 0; c < 8; c++) mod += g_h2p[c * 2048 + i];
            const float xv = base_metric[jj] + 0.1f * mod;
            const float sp = fmaxf(xv, 0.f) + log1pf(expf(-fabsf(xv)));
            g_md[i] = sp + 1e-6f;
        }
        __threadfence();
        if (tid == 0) g_c2 = 0u;
    }
}

// ---------------- sliding-window geometric interaction ----------------------
__global__ __launch_bounds__(256) void window_kernel()
{
    __shared__ float buf[8][32][33];
    const int widx = threadIdx.x >> 5;
    const int lane = threadIdx.x & 31;
    const int wg   = blockIdx.x * 8 + widx;
    const int b = wg >> 13;
    const int n = (wg >> 10) & 7;
    const int t = wg & 1023;

    const float* qbase = g_qv + (size_t)b * 1024 * 2048 + n * 128;
    const float* vbase = qbase + 1024;

    const float4 md = *(const float4*)(g_md + b * 1024 + n * 128 + lane * 4);
    const float4 qc = *(const float4*)(qbase + (size_t)t * 2048 + lane * 4);

    float (*mybuf)[33] = buf[widx];

    // phase 1: per-lane partial distances for all 32 window slots
#pragma unroll 1
    for (int k = 0; k < 32; k++) {
        const int row = t - 31 + k;
        float4 w = make_float4(0.f, 0.f, 0.f, 0.f);
        if (row >= 0) w = *(const float4*)(qbase + (size_t)row * 2048 + lane * 4);
        const float dx = qc.x - w.x, dy = qc.y - w.y;
        const float dz = qc.z - w.z, dw = qc.w - w.w;
        mybuf[k][lane] = md.x * dx * dx + md.y * dy * dy + md.z * dz * dz + md.w * dw * dw;
    }
    __syncwarp();

    // transpose-reduce: lane L sums window slot k=L (conflict-free, stride 33)
    float d0 = 0.f, d1 = 0.f, d2 = 0.f, d3 = 0.f;
#pragma unroll
    for (int i = 0; i < 32; i += 4) {
        d0 += mybuf[lane][i];     d1 += mybuf[lane][i + 1];
        d2 += mybuf[lane][i + 2]; d3 += mybuf[lane][i + 3];
    }
    const float e = __expf(-sqrtf((d0 + d1) + (d2 + d3) + 1e-8f));

    float sumw = e;
    float nq = qc.x * qc.x + qc.y * qc.y + qc.z * qc.z + qc.w * qc.w;
#pragma unroll
    for (int o = 16; o > 0; o >>= 1) {
        sumw += __shfl_xor_sync(0xffffffffu, sumw, o);
        nq   += __shfl_xor_sync(0xffffffffu, nq, o);
    }
    const float inv  = 1.f / (sumw + 1e-8f);
    const float invn = 1.f / fmaxf(sqrtf(nq), 1e-12f);

    // phase 2: weighted value aggregation
    float4 ctx = make_float4(0.f, 0.f, 0.f, 0.f);
#pragma unroll 1
    for (int k = 0; k < 32; k++) {
        const int row = t - 31 + k;
        const float wb = __shfl_sync(0xffffffffu, e, k) * inv;
        if (row >= 0) {
            const float4 v = *(const float4*)(vbase + (size_t)row * 2048 + lane * 4);
            ctx.x = fmaf(wb, v.x, ctx.x); ctx.y = fmaf(wb, v.y, ctx.y);
            ctx.z = fmaf(wb, v.z, ctx.z); ctx.w = fmaf(wb, v.w, ctx.w);
        }
    }

    const size_t oidx = (size_t)(b * 1024 + t) * 1024 + n * 128 + lane * 4;
    const float4 hb = *(const float4*)(g_heb + oidx);
    float4 o4;
    o4.x = rna_f(qc.x * (ctx.x + hb.x * invn));
    o4.y = rna_f(qc.y * (ctx.y + hb.y * invn));
    o4.z = rna_f(qc.z * (ctx.z + hb.z * invn));
    o4.w = rna_f(qc.w * (ctx.w + hb.w * invn));
    *(float4*)(g_g + oidx) = o4;
}

// ---------------- launch -----------------------------------------------------
extern "C" void kernel_launch(void* const* d_in, const int* in_sizes, int n_in,
                              void* d_out, int out_size)
{
    const float* x           = (const float*)d_in[0];
    const float* enc_q       = (const float*)d_in[1];
    const float* enc_v       = (const float*)d_in[2];
    const float* decoder     = (const float*)d_in[3];
    const float* hebbian     = (const float*)d_in[4];
    const float* m_w1        = (const float*)d_in[5];
    const float* m_b1        = (const float*)d_in[6];
    const float* m_w2        = (const float*)d_in[7];
    const float* m_b2        = (const float*)d_in[8];
    const float* base_metric = (const float*)d_in[9];
    float* out = (float*)d_out;

    static cudaStream_t s_side = nullptr;
    static cudaEvent_t ev_fork = nullptr, ev_enc = nullptr, ev_mlp = nullptr, ev_rndB = nullptr;
    static float *encB_p, *decB_p, *hebB_p;
    if (!s_side) {
        cudaStreamCreateWithFlags(&s_side, cudaStreamNonBlocking);
        cudaEventCreateWithFlags(&ev_fork, cudaEventDisableTiming);
        cudaEventCreateWithFlags(&ev_enc, cudaEventDisableTiming);
        cudaEventCreateWithFlags(&ev_mlp, cudaEventDisableTiming);
        cudaEventCreateWithFlags(&ev_rndB, cudaEventDisableTiming);
        cudaFuncSetAttribute(gemm_enc_kernel, cudaFuncAttributeMaxDynamicSharedMemorySize, SMEM_MT4);
        cudaFuncSetAttribute(gemm_dec_kernel, cudaFuncAttributeMaxDynamicSharedMemorySize, SMEM_MT2);
        cudaFuncSetAttribute(gemm_heb_kernel, cudaFuncAttributeMaxDynamicSharedMemorySize, SMEM_MT2);
        cudaGetSymbolAddress((void**)&encB_p, g_encB);
        cudaGetSymbolAddress((void**)&decB_p, g_decB);
        cudaGetSymbolAddress((void**)&hebB_p, g_hebB);
    }

    // fork FIRST (capture-legal): side stream enters capture via event wait
    cudaEventRecord(ev_fork, 0);
    cudaStreamWaitEvent(s_side, ev_fork, 0);

    // side: pre-round decoder+hebbian (independent; overlaps enc path)
    round2_kernel<<<1152, 256, 0, s_side>>>(
        (const float4*)decoder, (float4*)decB_p, 262144,
        (const float4*)hebbian, (float4*)hebB_p, 32768);
    cudaEventRecord(ev_rndB, s_side);

    // main: pre-round enc_q+enc_v, then enc GEMM
    round2_kernel<<<2048, 256>>>(
        (const float4*)enc_q, (float4*)encB_p, 262144,
        (const float4*)enc_v, (float4*)(encB_p + 1024u * 1024u), 262144);
    gemm_enc_kernel<<<dim3(16, 8), 256, SMEM_MT4>>>(x);

    // fork: MLP chain on side stream, heb GEMM on main stream (independent)
    cudaEventRecord(ev_enc, 0);
    cudaStreamWaitEvent(s_side, ev_enc, 0);
    mlp1_kernel<<<32, 256, 0, s_side>>>(m_w1, m_b1);
    mlp2_kernel<<<32, 256, 0, s_side>>>(m_w2, m_b2, base_metric);
    cudaEventRecord(ev_mlp, s_side);

    cudaStreamWaitEvent(0, ev_rndB, 0);
    gemm_heb_kernel<<<dim3(8, 16), 256, SMEM_MT2>>>();

    // join: window needs g_md (side stream) and g_heb (main stream)
    cudaStreamWaitEvent(0, ev_mlp, 0);
    window_kernel<<<2048, 256>>>();
    gemm_dec_kernel<<<dim3(8, 16), 256, SMEM_MT2>>>(out);
}

// round 16
// speedup vs baseline: 1.0258x; 1.0258x over previous
#include <cuda_runtime.h>
#include <math.h>
#include <stdint.h>

// Problem shapes (fixed): B=2, T=1024, D=1024, N=8, HD=128, K=32

// ---------------- scratch (device globals; no allocation allowed) ----------
__device__ float g_qv  [2048u * 2048u];  // rows = b*1024+t, [0,1024)=q, [1024,2048)=v
__device__ float g_decB[1024u * 1024u];      // rna(decoder)
__device__ float g_hebB[8u * 128u * 128u];   // rna(hebbian)
__device__ float g_sigp[8u * 1024u];     // sig partials: [mt(256-row tiles)][ct*128+c]
__device__ float g_h1p [16u * 1024u];    // mlp1 partials: [dchunk][b*512+j]
__device__ float g_h   [1024];           // [2][512]
__device__ float g_h2p [8u * 2048u];     // mlp2 partials: [ichunk][b*1024+j]
__device__ float g_md  [2048];           // [2][1024]
__device__ float g_heb [2048u * 1024u];  // hebbian context (un-normalized q basis)
__device__ float g_g   [2048u * 1024u];  // rna(q*(context+heb))
__device__ unsigned g_c1 = 0, g_c2 = 0;  // last-block counters (self-resetting)

// ---------------- helpers ----------------------------------------------------
__device__ __forceinline__ uint32_t smem_u32(const void* p) {
    uint32_t a;
    asm("{ .reg .u64 t; cvta.to.shared.u64 t, %1; cvt.u32.u64 %0, t; }" : "=r"(a) : "l"(p));
    return a;
}
__device__ __forceinline__ uint32_t rna_bits(float x) {
    uint32_t u; asm("cvt.rna.tf32.f32 %0, %1;" : "=r"(u) : "f"(x));
    return u;
}
__device__ __forceinline__ float rna_f(float x) {
    return __uint_as_float(rna_bits(x));
}
__device__ __forceinline__ void cp16(uint32_t dst, const void* src) {
    asm volatile("cp.async.cg.shared.global [%0], [%1], 16;" :: "r"(dst), "l"(src) : "memory");
}
__device__ __forceinline__ void mma_tf32_16n8k8(float* c, const uint32_t* a, const uint32_t* b) {
    asm volatile(
        "mma.sync.aligned.m16n8k8.row.col.f32.tf32.tf32.f32 "
        "{%0,%1,%2,%3}, {%4,%5,%6,%7}, {%8,%9}, {%0,%1,%2,%3};"
        : "+f"(c[0]), "+f"(c[1]), "+f"(c[2]), "+f"(c[3])
        : "r"(a[0]), "r"(a[1]), "r"(a[2]), "r"(a[3]), "r"(b[0]), "r"(b[1]));
}
__device__ __forceinline__ void f4fma(float4& a, float s, float4 w) {
    a.x = fmaf(s, w.x, a.x); a.y = fmaf(s, w.y, a.y);
    a.z = fmaf(s, w.z, a.z); a.w = fmaf(s, w.w, a.w);
}
__device__ __forceinline__ float4 f4add(float4 a, float4 b) {
    return make_float4(a.x + b.x, a.y + b.y, a.z + b.z, a.w + b.w);
}

// ---------------- pre-round: two tensors per launch --------------------------
__global__ void round2_kernel(const float4* __restrict__ s1, float4* __restrict__ d1, int n1,
                              const float4* __restrict__ s2, float4* __restrict__ d2, int n2)
{
    const int total = n1 + n2;
    for (int i = blockIdx.x * 256 + threadIdx.x; i < total; i += gridDim.x * 256) {
        const float4* s; float4* d; int j;
        if (i < n1) { s = s1; d = d1; j = i; }
        else        { s = s2; d = d2; j = i - n1; }
        float4 v = s[j];
        v.x = rna_f(v.x); v.y = rna_f(v.y);
        v.z = rna_f(v.z); v.w = rna_f(v.w);
        d[j] = v;
    }
}

// ---------------- tf32 mma.sync GEMM core -----------------------------------
// Block tile (64*MT) x 128, BK=32, 256 threads (8 warps: 4 in M x 2 in N),
// warp tile (16*MT) x 64. A row-major [.,lda], B row-major [K][N] (ldb).
// CVT_A/CVT_B: whether to RNA-round fragments at load (false = operand already
// tf32-rounded in gmem; HW truncation is then the identity).
#define A_STRIDE 36
#define B_STRIDE 136
#define B_SZ (32 * B_STRIDE)

template<int MT, bool RELU, bool CVT_A, bool CVT_B>
__device__ void gemm_mma_core(const float* __restrict__ A, int lda,
                              const float* __restrict__ B, int ldb,
                              float* __restrict__ C, int ldc, int Kdim,
                              float* __restrict__ sigp)
{
    extern __shared__ float smem[];
    constexpr int ROWS = 64 * MT;
    constexpr int ASZ  = ROWS * A_STRIDE;
    constexpr int STG  = ASZ + B_SZ;

    const int tid  = threadIdx.x;
    const int lane = tid & 31;
    const int wid  = tid >> 5;
    const int wm   = wid & 3;          // 0..3 -> (16*MT)-row slab
    const int wn   = wid >> 2;         // 0..1 -> 64-col slab
    const int grp  = lane >> 2;        // 0..7
    const int tig  = lane & 3;         // 0..3

    float acc[MT][8][4];
#pragma unroll
    for (int mt = 0; mt < MT; mt++)
#pragma unroll
        for (int nt = 0; nt < 8; nt++)
#pragma unroll
            for (int q = 0; q < 4; q++) acc[mt][nt][q] = 0.f;

    const int niter = Kdim >> 5;

    auto load_stage = [&](int S, int K0) {
        float* As_ = smem + S * STG;
        float* Bs_ = As_ + ASZ;
#pragma unroll
        for (int it = 0; it < 2 * MT; it++) {
            const int idx = tid + (it << 8);
            const int r_  = idx >> 3, c4_ = idx & 7;
            cp16(smem_u32(As_ + r_ * A_STRIDE + (c4_ << 2)),
                 A + (size_t)r_ * lda + K0 + (c4_ << 2));
        }
#pragma unroll
        for (int it = 0; it < 4; it++) {
            const int idx = tid + (it << 8);
            const int k_ = idx >> 5, n4_ = idx & 31;
            cp16(smem_u32(Bs_ + k_ * B_STRIDE + (n4_ << 2)),
                 B + (size_t)(K0 + k_) * ldb + (n4_ << 2));
        }
        asm volatile("cp.async.commit_group;" ::: "memory");
    };

    load_stage(0, 0);

#pragma unroll 1
    for (int j = 0; j < niter; j++) {
        if (j + 1 < niter) {
            load_stage((j + 1) & 1, (j + 1) << 5);
            asm volatile("cp.async.wait_group 1;" ::: "memory");
        } else {
            asm volatile("cp.async.wait_group 0;" ::: "memory");
        }
        __syncthreads();

        const float* As = smem + (j & 1) * STG;
        const float* Bs = As + ASZ;

#pragma unroll
        for (int kk = 0; kk < 4; kk++) {
            const int kb = kk << 3;
            uint32_t af[MT][4];
#pragma unroll
            for (int mt = 0; mt < MT; mt++) {
                const int r = wm * (16 * MT) + mt * 16 + grp;
                const float* ap = As + r * A_STRIDE + kb + tig;
                if (CVT_A) {
                    af[mt][0] = rna_bits(ap[0]);
                    af[mt][1] = rna_bits(ap[8 * A_STRIDE]);
                    af[mt][2] = rna_bits(ap[4]);
                    af[mt][3] = rna_bits(ap[8 * A_STRIDE + 4]);
                } else {
                    af[mt][0] = __float_as_uint(ap[0]);
                    af[mt][1] = __float_as_uint(ap[8 * A_STRIDE]);
                    af[mt][2] = __float_as_uint(ap[4]);
                    af[mt][3] = __float_as_uint(ap[8 * A_STRIDE + 4]);
                }
            }
            uint32_t bf[8][2];
#pragma unroll
            for (int nt = 0; nt < 8; nt++) {
                const int cc = wn * 64 + nt * 8 + grp;
                const float* bp = Bs + (kb + tig) * B_STRIDE + cc;
                if (CVT_B) {
                    bf[nt][0] = rna_bits(bp[0]);
                    bf[nt][1] = rna_bits(bp[4 * B_STRIDE]);
                } else {
                    bf[nt][0] = __float_as_uint(bp[0]);
                    bf[nt][1] = __float_as_uint(bp[4 * B_STRIDE]);
                }
            }
#pragma unroll
            for (int mt = 0; mt < MT; mt++)
#pragma unroll
                for (int nt = 0; nt < 8; nt++)
                    mma_tf32_16n8k8(acc[mt][nt], af[mt], bf[nt]);
        }
        __syncthreads();
    }

    // epilogue (+ optional fused sig accumulation)
    float csum[8][2];
#pragma unroll
    for (int nt = 0; nt < 8; nt++) { csum[nt][0] = 0.f; csum[nt][1] = 0.f; }

#pragma unroll
    for (int mt = 0; mt < MT; mt++) {
        const int r0 = wm * (16 * MT) + mt * 16 + grp;
#pragma unroll
        for (int nt = 0; nt < 8; nt++) {
            const int c0 = wn * 64 + nt * 8 + tig * 2;
            float2 v0 = make_float2(acc[mt][nt][0], acc[mt][nt][1]);
            float2 v1 = make_float2(acc[mt][nt][2], acc[mt][nt][3]);
            if (RELU) {
                v0.x = fmaxf(v0.x, 0.f); v0.y = fmaxf(v0.y, 0.f);
                v1.x = fmaxf(v1.x, 0.f); v1.y = fmaxf(v1.y, 0.f);
            }
            if (sigp) {
                csum[nt][0] += v0.x + v1.x;
                csum[nt][1] += v0.y + v1.y;
            }
            *(float2*)(C + (size_t)r0 * ldc + c0)       = v0;
            *(float2*)(C + (size_t)(r0 + 8) * ldc + c0) = v1;
        }
    }

    if (sigp) {
        // thread's rows are all == grp (mod 8) -> uniform time-weight
        const float w = (1.0f / 1024.0f) + ((grp == 0) ? (0.5f / 128.0f) : 0.f);
        float* sred = smem;      // safe: all threads past final k-loop sync
        if (tid < 128) sred[tid] = 0.f;
        __syncthreads();
#pragma unroll
        for (int nt = 0; nt < 8; nt++) {
            atomicAdd(&sred[wn * 64 + nt * 8 + tig * 2],     w * csum[nt][0]);
            atomicAdd(&sred[wn * 64 + nt * 8 + tig * 2 + 1], w * csum[nt][1]);
        }
        __syncthreads();
        if (tid < 128) sigp[tid] = sred[tid];   // non-atomic: block owns slot
    }
}

#define SMEM_MT2 (2 * (128 * A_STRIDE + B_SZ) * 4)   // 71680 B
#define SMEM_MT4 (2 * (256 * A_STRIDE + B_SZ) * 4)   // 108544 B

// enc: 256x128 tiles (MT=4). grid (16 ct, 8 mt).  A=x raw, B=raw enc (cvt both).
__global__ __launch_bounds__(256) void gemm_enc_kernel(
    const float* __restrict__ x, const float* __restrict__ enc_q,
    const float* __restrict__ enc_v)
{
    const int ct = blockIdx.x;   // 0..15: q heads then v heads
    const int mt = blockIdx.y;   // 0..7 (256-row tiles)
    const float* Bp = (ct < 8) ? (enc_q + (size_t)ct * 1024 * 128)
                               : (enc_v + (size_t)(ct - 8) * 1024 * 128);
    float* sigp = (ct < 8) ? (g_sigp + mt * 1024 + ct * 128) : nullptr;
    gemm_mma_core<4, true, true, true>(x + (size_t)mt * 256 * 1024, 1024, Bp, 128,
                           g_qv + (size_t)mt * 256 * 2048 + ct * 128, 2048, 1024, sigp);
}
// dec: 128x128 tiles (MT=2). A=g_g pre-rounded (window), B pre-rounded: cvt-free.
__global__ __launch_bounds__(256) void gemm_dec_kernel(float* __restrict__ out)
{
    const int nt = blockIdx.x;   // 0..7
    const int mt = blockIdx.y;   // 0..15
    gemm_mma_core<2, false, false, false>(g_g + (size_t)mt * 128 * 1024, 1024,
                            g_decB + nt * 128, 1024,
                            out + (size_t)mt * 128 * 1024 + nt * 128, 1024, 1024, nullptr);
}
// heb: 128x128 tiles (MT=2). A=raw q (cvt; normalization deferred), B pre-rounded.
__global__ __launch_bounds__(256) void gemm_heb_kernel()
{
    const int n  = blockIdx.x;   // 0..7 head
    const int mt = blockIdx.y;   // 0..15
    gemm_mma_core<2, false, true, false>(g_qv + (size_t)mt * 128 * 2048 + n * 128, 2048,
                            g_hebB + (size_t)n * 128 * 128, 128,
                            g_heb + (size_t)mt * 128 * 1024 + n * 128, 1024, 128, nullptr);
}

// ---------------- MLP layer 1: float4 partial GEMM + last-block finish ------
// grid 32: jb = bid&1 (256-j half), dc = bid>>1 (64-d chunk). 256 threads:
// j4 = tid&63 (64 float4 = 256 j), seg = tid>>6 (4 segs x 16 d).
__global__ void mlp1_kernel(const float* __restrict__ W1, const float* __restrict__ b1)
{
    __shared__ float ssig[2][64];
    __shared__ float4 red[4][2][64];
    __shared__ bool is_last;
    const int tid = threadIdx.x;
    const int jb  = blockIdx.x & 1;
    const int dc  = blockIdx.x >> 1;
    const int j4  = tid & 63;
    const int seg = tid >> 6;

    // gather sig chunk: sum 4 tile-partials per (b, d)  (256-row tiles)
    if (tid < 128) {
        const int b = tid >> 6, dl = tid & 63;
        float s = 0.f;
#pragma unroll
        for (int m = 0; m < 4; m++)
            s += g_sigp[(b * 4 + m) * 1024 + dc * 64 + dl];
        ssig[b][dl] = s;
    }
    __syncthreads();

    float4 acc0 = make_float4(0.f, 0.f, 0.f, 0.f);
    float4 acc1 = make_float4(0.f, 0.f, 0.f, 0.f);
#pragma unroll
    for (int i = 0; i < 16; i++) {
        const int dl = seg * 16 + i;
        const float4 w = ((const float4*)(W1 + (size_t)(dc * 64 + dl) * 512))[jb * 64 + j4];
        f4fma(acc0, ssig[0][dl], w);
        f4fma(acc1, ssig[1][dl], w);
    }
    red[seg][0][j4] = acc0;
    red[seg][1][j4] = acc1;
    __syncthreads();

    if (tid < 128) {
        const int b = tid >> 6, jj = tid & 63;
        float4 s = f4add(f4add(red[0][b][jj], red[1][b][jj]),
                         f4add(red[2][b][jj], red[3][b][jj]));
        *(float4*)&g_h1p[dc * 1024 + b * 512 + jb * 256 + jj * 4] = s;
    }

    __threadfence();
    if (tid == 0) is_last = (atomicAdd(&g_c1, 1u) == 31u);
    __syncthreads();
    if (is_last) {
        // finish: 256 float4 = 1024 values (b*512+j)
        const int i4 = tid;
        float4 a = ((const float4*)b1)[i4 & 127];
#pragma unroll
        for (int c = 0; c < 16; c++)
            a = f4add(a, ((const float4*)&g_h1p[c * 1024])[i4]);
        float4 o;
        o.x = 0.5f * a.x * (1.f + erff(a.x * 0.70710678118654752f));
        o.y = 0.5f * a.y * (1.f + erff(a.y * 0.70710678118654752f));
        o.z = 0.5f * a.z * (1.f + erff(a.z * 0.70710678118654752f));
        o.w = 0.5f * a.w * (1.f + erff(a.w * 0.70710678118654752f));
        ((float4*)g_h)[i4] = o;
        __threadfence();
        if (tid == 0) g_c1 = 0u;
    }
}

// ---------------- MLP layer 2: float4 partial GEMM + last-block finish ------
// grid 32: jb = bid&3 (256-j quarter), ic = bid>>2 (64-i chunk). 256 threads:
// j4 = tid&63, seg = tid>>6 (4 segs x 16 i).
__global__ void mlp2_kernel(const float* __restrict__ W2, const float* __restrict__ b2,
                            const float* __restrict__ base_metric)
{
    __shared__ float sh[2][64];
    __shared__ float4 red[4][2][64];
    __shared__ bool is_last;
    const int tid = threadIdx.x;
    const int jb  = blockIdx.x & 3;
    const int ic  = blockIdx.x >> 2;
    const int j4  = tid & 63;
    const int seg = tid >> 6;

    if (tid < 128) {
        const int b = tid >> 6, il = tid & 63;
        sh[b][il] = g_h[b * 512 + ic * 64 + il];
    }
    __syncthreads();

    float4 acc0 = make_float4(0.f, 0.f, 0.f, 0.f);
    float4 acc1 = make_float4(0.f, 0.f, 0.f, 0.f);
#pragma unroll
    for (int i = 0; i < 16; i++) {
        const int il = seg * 16 + i;
        const float4 w = ((const float4*)(W2 + (size_t)(ic * 64 + il) * 1024))[jb * 64 + j4];
        f4fma(acc0, sh[0][il], w);
        f4fma(acc1, sh[1][il], w);
    }
    red[seg][0][j4] = acc0;
    red[seg][1][j4] = acc1;
    __syncthreads();

    if (tid < 128) {
        const int b = tid >> 6, jj = tid & 63;
        float4 s = f4add(f4add(red[0][b][jj], red[1][b][jj]),
                         f4add(red[2][b][jj], red[3][b][jj]));
        *(float4*)&g_h2p[ic * 2048 + b * 1024 + jb * 256 + jj * 4] = s;
    }

    __threadfence();
    if (tid == 0) is_last = (atomicAdd(&g_c2, 1u) == 31u);
    __syncthreads();
    if (is_last) {
        // finish: 512 float4 = 2048 values (b*1024+j)
#pragma unroll
        for (int q = 0; q < 2; q++) {
            const int i4 = q * 256 + tid;
            float4 mod = ((const float4*)b2)[i4 & 255];
#pragma unroll
            for (int c = 0; c < 8; c++)
                mod = f4add(mod, ((const float4*)&g_h2p[c * 2048])[i4]);
            const float4 bm = ((const float4*)base_metric)[i4 & 255];
            float4 o;
            {
                float xv = bm.x + 0.1f * mod.x;
                o.x = fmaxf(xv, 0.f) + log1pf(expf(-fabsf(xv))) + 1e-6f;
                xv = bm.y + 0.1f * mod.y;
                o.y = fmaxf(xv, 0.f) + log1pf(expf(-fabsf(xv))) + 1e-6f;
                xv = bm.z + 0.1f * mod.z;
                o.z = fmaxf(xv, 0.f) + log1pf(expf(-fabsf(xv))) + 1e-6f;
                xv = bm.w + 0.1f * mod.w;
                o.w = fmaxf(xv, 0.f) + log1pf(expf(-fabsf(xv))) + 1e-6f;
            }
            ((float4*)g_md)[i4] = o;
        }
        __threadfence();
        if (tid == 0) g_c2 = 0u;
    }
}

// ---------------- sliding-window geometric interaction ----------------------
__global__ __launch_bounds__(256) void window_kernel()
{
    __shared__ float buf[8][32][33];
    const int widx = threadIdx.x >> 5;
    const int lane = threadIdx.x & 31;
    const int wg   = blockIdx.x * 8 + widx;
    const int b = wg >> 13;
    const int n = (wg >> 10) & 7;
    const int t = wg & 1023;

    const float* qbase = g_qv + (size_t)b * 1024 * 2048 + n * 128;
    const float* vbase = qbase + 1024;

    const float4 md = *(const float4*)(g_md + b * 1024 + n * 128 + lane * 4);
    const float4 qc = *(const float4*)(qbase + (size_t)t * 2048 + lane * 4);

    float (*mybuf)[33] = buf[widx];

    // phase 1: per-lane partial distances for all 32 window slots
#pragma unroll 1
    for (int k = 0; k < 32; k++) {
        const int row = t - 31 + k;
        float4 w = make_float4(0.f, 0.f, 0.f, 0.f);
        if (row >= 0) w = *(const float4*)(qbase + (size_t)row * 2048 + lane * 4);
        const float dx = qc.x - w.x, dy = qc.y - w.y;
        const float dz = qc.z - w.z, dw = qc.w - w.w;
        mybuf[k][lane] = md.x * dx * dx + md.y * dy * dy + md.z * dz * dz + md.w * dw * dw;
    }
    __syncwarp();

    // transpose-reduce: lane L sums window slot k=L (conflict-free, stride 33)
    float d0 = 0.f, d1 = 0.f, d2 = 0.f, d3 = 0.f;
#pragma unroll
    for (int i = 0; i < 32; i += 4) {
        d0 += mybuf[lane][i];     d1 += mybuf[lane][i + 1];
        d2 += mybuf[lane][i + 2]; d3 += mybuf[lane][i + 3];
    }
    const float e = __expf(-sqrtf((d0 + d1) + (d2 + d3) + 1e-8f));

    float sumw = e;
    float nq = qc.x * qc.x + qc.y * qc.y + qc.z * qc.z + qc.w * qc.w;
#pragma unroll
    for (int o = 16; o > 0; o >>= 1) {
        sumw += __shfl_xor_sync(0xffffffffu, sumw, o);
        nq   += __shfl_xor_sync(0xffffffffu, nq, o);
    }
    const float inv  = 1.f / (sumw + 1e-8f);
    const float invn = 1.f / fmaxf(sqrtf(nq), 1e-12f);

    // phase 2: weighted value aggregation
    float4 ctx = make_float4(0.f, 0.f, 0.f, 0.f);
#pragma unroll 1
    for (int k = 0; k < 32; k++) {
        const int row = t - 31 + k;
        const float wb = __shfl_sync(0xffffffffu, e, k) * inv;
        if (row >= 0) {
            const float4 v = *(const float4*)(vbase + (size_t)row * 2048 + lane * 4);
            ctx.x = fmaf(wb, v.x, ctx.x); ctx.y = fmaf(wb, v.y, ctx.y);
            ctx.z = fmaf(wb, v.z, ctx.z); ctx.w = fmaf(wb, v.w, ctx.w);
        }
    }

    const size_t oidx = (size_t)(b * 1024 + t) * 1024 + n * 128 + lane * 4;
    const float4 hb = *(const float4*)(g_heb + oidx);
    float4 o4;
    o4.x = rna_f(qc.x * (ctx.x + hb.x * invn));
    o4.y = rna_f(qc.y * (ctx.y + hb.y * invn));
    o4.z = rna_f(qc.z * (ctx.z + hb.z * invn));
    o4.w = rna_f(qc.w * (ctx.w + hb.w * invn));
    *(float4*)(g_g + oidx) = o4;
}

// ---------------- launch -----------------------------------------------------
extern "C" void kernel_launch(void* const* d_in, const int* in_sizes, int n_in,
                              void* d_out, int out_size)
{
    const float* x           = (const float*)d_in[0];
    const float* enc_q       = (const float*)d_in[1];
    const float* enc_v       = (const float*)d_in[2];
    const float* decoder     = (const float*)d_in[3];
    const float* hebbian     = (const float*)d_in[4];
    const float* m_w1        = (const float*)d_in[5];
    const float* m_b1        = (const float*)d_in[6];
    const float* m_w2        = (const float*)d_in[7];
    const float* m_b2        = (const float*)d_in[8];
    const float* base_metric = (const float*)d_in[9];
    float* out = (float*)d_out;

    static cudaStream_t s_side = nullptr;
    static cudaEvent_t ev_fork = nullptr, ev_enc = nullptr, ev_mlp = nullptr, ev_rndB = nullptr;
    static float *decB_p, *hebB_p;
    if (!s_side) {
        cudaStreamCreateWithFlags(&s_side, cudaStreamNonBlocking);
        cudaEventCreateWithFlags(&ev_fork, cudaEventDisableTiming);
        cudaEventCreateWithFlags(&ev_enc, cudaEventDisableTiming);
        cudaEventCreateWithFlags(&ev_mlp, cudaEventDisableTiming);
        cudaEventCreateWithFlags(&ev_rndB, cudaEventDisableTiming);
        cudaFuncSetAttribute(gemm_enc_kernel, cudaFuncAttributeMaxDynamicSharedMemorySize, SMEM_MT4);
        cudaFuncSetAttribute(gemm_dec_kernel, cudaFuncAttributeMaxDynamicSharedMemorySize, SMEM_MT2);
        cudaFuncSetAttribute(gemm_heb_kernel, cudaFuncAttributeMaxDynamicSharedMemorySize, SMEM_MT2);
        cudaGetSymbolAddress((void**)&decB_p, g_decB);
        cudaGetSymbolAddress((void**)&hebB_p, g_hebB);
    }

    // fork FIRST (capture-legal): side stream enters capture via event wait
    cudaEventRecord(ev_fork, 0);
    cudaStreamWaitEvent(s_side, ev_fork, 0);

    // side: pre-round decoder+hebbian (independent; overlaps enc GEMM)
    round2_kernel<<<1152, 256, 0, s_side>>>(
        (const float4*)decoder, (float4*)decB_p, 262144,
        (const float4*)hebbian, (float4*)hebB_p, 32768);
    cudaEventRecord(ev_rndB, s_side);

    // main: enc GEMM directly on raw inputs
    gemm_enc_kernel<<<dim3(16, 8), 256, SMEM_MT4>>>(x, enc_q, enc_v);

    // fork: MLP chain on side stream, heb GEMM on main stream (independent)
    cudaEventRecord(ev_enc, 0);
    cudaStreamWaitEvent(s_side, ev_enc, 0);
    mlp1_kernel<<<32, 256, 0, s_side>>>(m_w1, m_b1);
    mlp2_kernel<<<32, 256, 0, s_side>>>(m_w2, m_b2, base_metric);
    cudaEventRecord(ev_mlp, s_side);

    cudaStreamWaitEvent(0, ev_rndB, 0);
    gemm_heb_kernel<<<dim3(8, 16), 256, SMEM_MT2>>>();

    // join: window needs g_md (side stream) and g_heb (main stream)
    cudaStreamWaitEvent(0, ev_mlp, 0);
    window_kernel<<<2048, 256>>>();
    gemm_dec_kernel<<<dim3(8, 16), 256, SMEM_MT2>>>(out);
}